// round 14
// baseline (speedup 1.0000x reference)
#include <cuda_runtime.h>
#include <cuda_fp16.h>
#include <cstdint>

#define NC 16
#define S_DIM 512
#define D_DIM 256
#define O_DIM 512
#define B_DIM 256

__device__ __half g_xs[(size_t)B_DIM * S_DIM * D_DIM];   // x fp16 [b][s][k]
__device__ float  g_xsum[B_DIM * D_DIM];                 // per-batch column sums of x
__device__ __half g_ws[D_DIM * O_DIM];                   // W fp16 [k][o] (logits only)

// ---------------- PTX helpers ----------------
#define LDMX4(r, addr)                                                                   \
    asm volatile("ldmatrix.sync.aligned.m8n8.x4.shared.b16 {%0,%1,%2,%3}, [%4];"         \
                 : "=r"((r)[0]), "=r"((r)[1]), "=r"((r)[2]), "=r"((r)[3]) : "r"(addr))
#define LDMX4T(r, addr)                                                                  \
    asm volatile("ldmatrix.sync.aligned.m8n8.x4.trans.shared.b16 {%0,%1,%2,%3}, [%4];"   \
                 : "=r"((r)[0]), "=r"((r)[1]), "=r"((r)[2]), "=r"((r)[3]) : "r"(addr))
#define MMA_FP16(d, a, b0, b1)                                                           \
    asm volatile("mma.sync.aligned.m16n8k16.row.col.f32.f16.f16.f32 "                    \
                 "{%0,%1,%2,%3}, {%4,%5,%6,%7}, {%8,%9}, {%0,%1,%2,%3};"                 \
                 : "+f"((d)[0]), "+f"((d)[1]), "+f"((d)[2]), "+f"((d)[3])                \
                 : "r"((a)[0]), "r"((a)[1]), "r"((a)[2]), "r"((a)[3]), "r"(b0), "r"(b1))
#define CP16(dst, src)                                                                   \
    asm volatile("cp.async.cg.shared.global [%0], [%1], 16;" :: "r"(dst), "l"(src))
#define CPCOMMIT() asm volatile("cp.async.commit_group;")
#define CPWAIT(n)  asm volatile("cp.async.wait_group %0;" :: "n"(n))

__device__ __forceinline__ uint32_t smem_u32(const void* p) {
    uint32_t a;
    asm("{ .reg .u64 t; cvta.to.shared.u64 t, %1; cvt.u32.u64 %0, t; }" : "=r"(a) : "l"(p));
    return a;
}

// ---------------- split_x: fp16 convert + per-batch column sums ----------------
__global__ __launch_bounds__(256) void split_x(const float* __restrict__ x) {
    __shared__ float sums[4][256];
    const int b = blockIdx.x, t = threadIdx.x;
    const int kq = t & 63;   // float4 group within k
    const int sg = t >> 6;   // 0..3
    float4 s4 = make_float4(0.f, 0.f, 0.f, 0.f);
    for (int s = sg; s < S_DIM; s += 4) {
        const size_t base = ((size_t)(b * S_DIM + s)) * D_DIM + kq * 4;
        const float4 f = *(const float4*)&x[base];
        __half2 h0 = __floats2half2_rn(f.x, f.y);
        __half2 h1 = __floats2half2_rn(f.z, f.w);
        *(uint2*)&g_xs[base] = make_uint2(*(uint32_t*)&h0, *(uint32_t*)&h1);
        s4.x += f.x; s4.y += f.y; s4.z += f.z; s4.w += f.w;
    }
    *(float4*)&sums[sg][kq * 4] = s4;
    __syncthreads();
    g_xsum[b * 256 + t] = sums[0][t] + sums[1][t] + sums[2][t] + sums[3][t];
}

__global__ __launch_bounds__(256) void split_w(const float* __restrict__ W) {
    const int i = blockIdx.x * 256 + threadIdx.x;
    g_ws[i] = __float2half(W[i]);
}

// ---------------- routing: one CTA per batch, everything fused ----------------
// smem byte offsets
#define XT_STR 264           // halfs per x-tile row (256 + 8 pad)
#define GC_STR 24            // halfs per G/C row (16 + 8 pad)
#define SM_XT0   0           // x tile buf0: 64*264*2 = 33792
#define SM_XT1   33792
#define SM_G     67584       // G [256 k][24] fp16 = 12288
#define SM_C     79872       // c [64 s][24] fp16 = 3072
#define SM_L     82944       // logits [64][17] fp32 = 4352
#define SM_Y     87296       // y^T [256 k][17] fp32 = 17408
#define SM_OUT   104704      // out [512] fp32 = 2048
#define SM_XSUM  106752      // xsum [256] fp32 = 1024
#define SM_TOTAL 107776

__device__ __forceinline__ void issue_tile(uint32_t smb, int buf, const __half* gx,
                                           int tile, int ldr, int ldc0) {
    const uint32_t dst = smb + (uint32_t)buf * 33792u + (uint32_t)(ldr * XT_STR * 2);
    const uint64_t src = __cvta_generic_to_global(gx + (size_t)(tile * 64 + ldr) * D_DIM);
#pragma unroll
    for (int j = 0; j < 8; j++)
        CP16(dst + (uint32_t)(ldc0 + j) * 16u, src + (uint64_t)(ldc0 + j) * 16u);
    CPCOMMIT();
}

__global__ __launch_bounds__(256, 2) void caps_routing(const float* __restrict__ W,
                                                       float* __restrict__ out) {
    extern __shared__ char sm[];
    const uint32_t smb = smem_u32(sm);
    float* outsm = (float*)(sm + SM_OUT);
    float* xsum  = (float*)(sm + SM_XSUM);
    float* Lsm   = (float*)(sm + SM_L);
    float* Ysm   = (float*)(sm + SM_Y);
    __half* Gsm  = (__half*)(sm + SM_G);
    __half* Csm  = (__half*)(sm + SM_C);

    const int b = blockIdx.x;
    const int t = threadIdx.x;
    const int lane = t & 31, w = t >> 5;
    const int mat = lane >> 3, rr = lane & 7;
    const __half* gx = g_xs + (size_t)b * S_DIM * D_DIM;

    xsum[t] = g_xsum[b * 256 + t];
    __syncthreads();

    // ---- out0 = squash(xsum·W / 16) ----
    {
        float v0 = 0.f, v1 = 0.f;
#pragma unroll 4
        for (int k = 0; k < 256; k++) {
            const float xv = xsum[k];
            v0 += xv * W[(size_t)k * 512 + t];
            v1 += xv * W[(size_t)k * 512 + t + 256];
        }
        v0 *= (1.f / 16.f); v1 *= (1.f / 16.f);
        float ss0 = v0 * v0, ss1 = v1 * v1;
#pragma unroll
        for (int o = 16; o > 0; o >>= 1) {
            ss0 += __shfl_xor_sync(0xffffffffu, ss0, o);
            ss1 += __shfl_xor_sync(0xffffffffu, ss1, o);
        }
        outsm[t] = v0 / sqrtf(ss0 + 1e-7f);
        outsm[t + 256] = v1 / sqrtf(ss1 + 1e-7f);
    }
    __syncthreads();

    // frag offsets (old proven patterns)
    const int wmA = w >> 1, wnA = w & 1;  // phase A: s0 = wmA*16, n8 = wnA
    const uint32_t xtA_off = (uint32_t)(((wmA * 16 + (mat & 1) * 8 + rr) * XT_STR + (mat >> 1) * 8) * 2);
    const uint32_t gc_off  = (uint32_t)((((mat & 1) * 8 + rr) * GC_STR + (mat >> 1) * 8) * 2);
    // phase B A-frag (x^T via trans): row = (mat>>1)*8+rr, col = w*32 + (mat&1)*8
    const uint32_t xtB_off = (uint32_t)((((mat >> 1) * 8 + rr) * XT_STR + w * 32 + (mat & 1) * 8) * 2);

    const int ldr = t >> 2;            // tile-load row
    const int ldc0 = (t & 3) * 8;      // tile-load chunk base

    for (int it = 1; it <= 2; it++) {
        // ---- G[k][n] = Σ_d g_ws[k][n*32+d]·outsm[n*32+d]  (fp16) ----
        {
            const int gn = t & 15, kg = t >> 4;
            for (int kk = kg * 16; kk < kg * 16 + 16; kk++) {
                float acc = 0.f;
#pragma unroll
                for (int d2 = 0; d2 < 16; d2++) {
                    const float2 wf = __half22float2(
                        *(const __half2*)&g_ws[(size_t)kk * 512 + gn * 32 + d2 * 2]);
                    acc += wf.x * outsm[gn * 32 + d2 * 2] + wf.y * outsm[gn * 32 + d2 * 2 + 1];
                }
                Gsm[kk * GC_STR + gn] = __float2half(acc);
            }
        }
        __syncthreads();

        float accB[2][2][4];
#pragma unroll
        for (int i = 0; i < 2; i++)
#pragma unroll
            for (int j = 0; j < 2; j++)
#pragma unroll
                for (int q = 0; q < 4; q++) accB[i][j][q] = 0.f;

        issue_tile(smb, 0, gx, 0, ldr, ldc0);
        for (int tile = 0; tile < 8; tile++) {
            if (tile < 7) { issue_tile(smb, (tile + 1) & 1, gx, tile + 1, ldr, ldc0); CPWAIT(1); }
            else CPWAIT(0);
            __syncthreads();
            const uint32_t xb = smb + (uint32_t)(tile & 1) * 33792u;

            // phase A: logits D[s16, n8] = Σ_k x·G
            float accA[4] = {0.f, 0.f, 0.f, 0.f};
#pragma unroll
            for (int ks = 0; ks < 16; ks++) {
                uint32_t Af[4], Bf[4];
                LDMX4(Af, xb + xtA_off + ks * 32);
                LDMX4T(Bf, smb + SM_G + gc_off + (uint32_t)(ks * 16 * GC_STR * 2));
                MMA_FP16(accA, Af, Bf[wnA * 2], Bf[wnA * 2 + 1]);
            }
            {
                const int sl = wmA * 16 + (lane >> 2);
                const int nc = wnA * 8 + (lane & 3) * 2;
                Lsm[sl * 17 + nc] = accA[0];
                Lsm[sl * 17 + nc + 1] = accA[1];
                Lsm[(sl + 8) * 17 + nc] = accA[2];
                Lsm[(sl + 8) * 17 + nc + 1] = accA[3];
            }
            __syncthreads();

            // softmax over n per s (64 threads)
            if (t < 64) {
                float bv[16];
                float mx = -1e30f;
#pragma unroll
                for (int n = 0; n < 16; n++) { bv[n] = Lsm[t * 17 + n]; mx = fmaxf(mx, bv[n]); }
                float den = 0.f;
#pragma unroll
                for (int n = 0; n < 16; n++) { bv[n] = __expf(bv[n] - mx); den += bv[n]; }
                const float inv = 1.f / den;
#pragma unroll
                for (int n = 0; n < 16; n += 2)
                    *(__half2*)&Csm[t * GC_STR + n] =
                        __floats2half2_rn(bv[n] * inv, bv[n + 1] * inv);
            }
            __syncthreads();

            // phase B: y^T[k32, n16] += Σ_s x^T·c
#pragma unroll
            for (int ks = 0; ks < 4; ks++) {
                uint32_t Bf[4];
                LDMX4T(Bf, smb + SM_C + gc_off + (uint32_t)(ks * 16 * GC_STR * 2));
#pragma unroll
                for (int mf = 0; mf < 2; mf++) {
                    uint32_t Af[4];
                    LDMX4T(Af, xb + xtB_off + (uint32_t)(mf * 16 * 2) +
                               (uint32_t)(ks * 16 * XT_STR * 2));
                    MMA_FP16(accB[mf][0], Af, Bf[0], Bf[1]);
                    MMA_FP16(accB[mf][1], Af, Bf[2], Bf[3]);
                }
            }
            __syncthreads();
        }

        // ---- write y^T to smem ----
#pragma unroll
        for (int mf = 0; mf < 2; mf++) {
            const int kx = w * 32 + mf * 16 + (lane >> 2);
#pragma unroll
            for (int h = 0; h < 2; h++) {
                const int nc = h * 8 + (lane & 3) * 2;
                Ysm[kx * 17 + nc] = accB[mf][h][0];
                Ysm[kx * 17 + nc + 1] = accB[mf][h][1];
                Ysm[(kx + 8) * 17 + nc] = accB[mf][h][2];
                Ysm[(kx + 8) * 17 + nc + 1] = accB[mf][h][3];
            }
        }
        __syncthreads();

        // ---- out_it = squash(y·W) ----
        {
            const int na = t >> 5;
            const int nb = (t + 256) >> 5;
            float v0 = 0.f, v1 = 0.f;
#pragma unroll 4
            for (int k = 0; k < 256; k++) {
                v0 += Ysm[k * 17 + na] * W[(size_t)k * 512 + t];
                v1 += Ysm[k * 17 + nb] * W[(size_t)k * 512 + t + 256];
            }
            float ss0 = v0 * v0, ss1 = v1 * v1;
#pragma unroll
            for (int o = 16; o > 0; o >>= 1) {
                ss0 += __shfl_xor_sync(0xffffffffu, ss0, o);
                ss1 += __shfl_xor_sync(0xffffffffu, ss1, o);
            }
            const float r0 = v0 / sqrtf(ss0 + 1e-7f);
            const float r1 = v1 / sqrtf(ss1 + 1e-7f);
            if (it == 2) {
                out[(size_t)b * 512 + t] = r0;
                out[(size_t)b * 512 + t + 256] = r1;
            } else {
                outsm[t] = r0;
                outsm[t + 256] = r1;
            }
        }
        __syncthreads();
    }
}

extern "C" void kernel_launch(void* const* d_in, const int* in_sizes, int n_in,
                              void* d_out, int out_size) {
    const float* x = (const float*)d_in[0];
    const float* W = (const float*)d_in[1];
    float* out = (float*)d_out;

    split_x<<<B_DIM, 256>>>(x);
    split_w<<<512, 256>>>(W);
    cudaFuncSetAttribute(caps_routing, cudaFuncAttributeMaxDynamicSharedMemorySize, SM_TOTAL);
    caps_routing<<<B_DIM, 256, SM_TOTAL>>>(W, out);
}

// round 15
// speedup vs baseline: 1.1270x; 1.1270x over previous
#include <cuda_runtime.h>
#include <cuda_fp16.h>
#include <cstdint>

#define NC 16
#define S_DIM 512
#define D_DIM 256
#define O_DIM 512
#define B_DIM 256

__device__ __half g_xs[(size_t)B_DIM * S_DIM * D_DIM];   // x fp16 [b][s][k]
__device__ float  g_xsum[B_DIM * D_DIM];                 // per-batch col sums of x
__device__ __half g_ws[D_DIM * O_DIM];                   // W fp16 (logit path)
__device__ __half g_G[(size_t)B_DIM * D_DIM * NC];       // G [b][k][n] fp16
__device__ float  g_y[(size_t)B_DIM * D_DIM * NC];       // y [b][k][n] fp32
__device__ float  g_out[B_DIM * O_DIM];                  // routed outputs (intermediate)

// ---------------- PTX helpers ----------------
#define LDMX4(r, addr)                                                                   \
    asm volatile("ldmatrix.sync.aligned.m8n8.x4.shared.b16 {%0,%1,%2,%3}, [%4];"         \
                 : "=r"((r)[0]), "=r"((r)[1]), "=r"((r)[2]), "=r"((r)[3]) : "r"(addr))
#define LDMX4T(r, addr)                                                                  \
    asm volatile("ldmatrix.sync.aligned.m8n8.x4.trans.shared.b16 {%0,%1,%2,%3}, [%4];"   \
                 : "=r"((r)[0]), "=r"((r)[1]), "=r"((r)[2]), "=r"((r)[3]) : "r"(addr))
#define MMA_FP16(d, a, b0, b1)                                                           \
    asm volatile("mma.sync.aligned.m16n8k16.row.col.f32.f16.f16.f32 "                    \
                 "{%0,%1,%2,%3}, {%4,%5,%6,%7}, {%8,%9}, {%0,%1,%2,%3};"                 \
                 : "+f"((d)[0]), "+f"((d)[1]), "+f"((d)[2]), "+f"((d)[3])                \
                 : "r"((a)[0]), "r"((a)[1]), "r"((a)[2]), "r"((a)[3]), "r"(b0), "r"(b1))
#define CP16(dst, src)                                                                   \
    asm volatile("cp.async.cg.shared.global [%0], [%1], 16;" :: "r"(dst), "l"(src))
#define CPCOMMIT() asm volatile("cp.async.commit_group;")
#define CPWAIT(n)  asm volatile("cp.async.wait_group %0;" :: "n"(n))

__device__ __forceinline__ uint32_t smem_u32(const void* p) {
    uint32_t a;
    asm("{ .reg .u64 t; cvta.to.shared.u64 t, %1; cvt.u32.u64 %0, t; }" : "=r"(a) : "l"(p));
    return a;
}

// ---------------- split_w: W->fp16, zero xsum ----------------
__global__ __launch_bounds__(256) void split_w(const float* __restrict__ W) {
    const int i = blockIdx.x * 256 + threadIdx.x;
    g_ws[i] = __float2half(W[i]);
    if (blockIdx.x < 256) g_xsum[i] = 0.f;
}

// ---------------- split_x: convert + partial col sums (grid 256 x 4) ----------------
__global__ __launch_bounds__(256) void split_x(const float* __restrict__ x) {
    __shared__ float sums[4][256];
    const int b = blockIdx.x, sq = blockIdx.y, t = threadIdx.x;
    const int kq = t & 63, sg = t >> 6;
    float4 s4 = make_float4(0.f, 0.f, 0.f, 0.f);
    for (int s = sq * 128 + sg; s < sq * 128 + 128; s += 4) {
        const size_t base = ((size_t)(b * S_DIM + s)) * D_DIM + kq * 4;
        const float4 f = *(const float4*)&x[base];
        __half2 h0 = __floats2half2_rn(f.x, f.y);
        __half2 h1 = __floats2half2_rn(f.z, f.w);
        *(uint2*)&g_xs[base] = make_uint2(*(uint32_t*)&h0, *(uint32_t*)&h1);
        s4.x += f.x; s4.y += f.y; s4.z += f.z; s4.w += f.w;
    }
    *(float4*)&sums[sg][kq * 4] = s4;
    __syncthreads();
    atomicAdd(&g_xsum[b * 256 + t], sums[0][t] + sums[1][t] + sums[2][t] + sums[3][t]);
}

// ---------------- squash_k: out[b] = squash(scale * Y[b] . W_n) ----------------
// grid (16 n, 8 bgroup), block 256 = 32 d x 8 bsub
__global__ __launch_bounds__(256) void squash_k(const float* __restrict__ W,
                                                int mode,      // 0: Y = xsum (scaled 1/16), 1: Y = g_y
                                                int final,     // write to out vs g_out
                                                float* __restrict__ outp) {
    __shared__ float Wsm[256 * 33];
    const int n = blockIdx.x, bg = blockIdx.y, t = threadIdx.x;
#pragma unroll
    for (int d = 0; d < 32; d++)
        Wsm[t * 33 + d] = W[(size_t)t * 512 + n * 32 + d];
    __syncthreads();

    const int d = t & 31, bsub = t >> 5;
    float acc[4] = {0.f, 0.f, 0.f, 0.f};
    int bidx[4];
#pragma unroll
    for (int j = 0; j < 4; j++) bidx[j] = bg * 32 + bsub + 8 * j;

#pragma unroll 2
    for (int k = 0; k < 256; k++) {
        const float wv = Wsm[k * 33 + d];
#pragma unroll
        for (int j = 0; j < 4; j++) {
            const float yv = mode ? g_y[((size_t)(bidx[j] * 256 + k)) * 16 + n]
                                  : g_xsum[bidx[j] * 256 + k];
            acc[j] += yv * wv;
        }
    }
#pragma unroll
    for (int j = 0; j < 4; j++) {
        float v = mode ? acc[j] : acc[j] * (1.f / 16.f);
        float ss = v * v;
#pragma unroll
        for (int o = 16; o > 0; o >>= 1) ss += __shfl_xor_sync(0xffffffffu, ss, o);
        const float r = v / sqrtf(ss + 1e-7f);
        if (final) outp[(size_t)bidx[j] * 512 + n * 32 + d] = r;
        else g_out[bidx[j] * 512 + n * 32 + d] = r;
    }
}

// ---------------- gmat_k: G[b][k][n] = sum_d W[k][n*32+d] * out[b][n*32+d] ----------------
// grid (16 n, 8 bgroup), block 256 = k
__global__ __launch_bounds__(256) void gmat_k(const float* __restrict__ W) {
    __shared__ float Wsm[256 * 33];
    __shared__ float osm[32 * 33];
    const int n = blockIdx.x, bg = blockIdx.y, t = threadIdx.x;
#pragma unroll
    for (int d = 0; d < 32; d++)
        Wsm[t * 33 + d] = W[(size_t)t * 512 + n * 32 + d];
#pragma unroll
    for (int r = 0; r < 4; r++) {
        const int idx = t + 256 * r;
        const int bl = idx >> 5, d = idx & 31;
        osm[bl * 33 + d] = g_out[(bg * 32 + bl) * 512 + n * 32 + d];
    }
    __syncthreads();

    const int k = t;
    for (int bl = 0; bl < 32; bl++) {
        float a0 = 0.f, a1 = 0.f;
#pragma unroll
        for (int d = 0; d < 32; d += 2) {
            a0 += osm[bl * 33 + d] * Wsm[k * 33 + d];
            a1 += osm[bl * 33 + d + 1] * Wsm[k * 33 + d + 1];
        }
        g_G[((size_t)((bg * 32 + bl) * 256 + k)) * 16 + n] = __float2half(a0 + a1);
    }
}

// ---------------- route_pass: per-batch tile loop (R14-verified mma mappings) ----------------
#define XT_STR 264
#define GC_STR 24
#define SM_XT0   0           // 64*264*2 = 33792
#define SM_XT1   33792
#define SM_G     67584       // 256*24*2 = 12288
#define SM_C     79872       // 64*24*2 = 3072
#define SM_L     82944       // 64*17*4 = 4352
#define SM_TOTAL 87296

__device__ __forceinline__ void issue_tile(uint32_t smb, int buf, const __half* gx,
                                           int tile, int ldr, int ldc0) {
    const uint32_t dst = smb + (uint32_t)buf * 33792u + (uint32_t)(ldr * XT_STR * 2);
    const uint64_t src = __cvta_generic_to_global(gx + (size_t)(tile * 64 + ldr) * D_DIM);
#pragma unroll
    for (int j = 0; j < 8; j++)
        CP16(dst + (uint32_t)(ldc0 + j) * 16u, src + (uint64_t)(ldc0 + j) * 16u);
    CPCOMMIT();
}

__global__ __launch_bounds__(256, 2) void route_pass() {
    extern __shared__ char sm[];
    const uint32_t smb = smem_u32(sm);
    float* Lsm  = (float*)(sm + SM_L);
    __half* Gsm = (__half*)(sm + SM_G);
    __half* Csm = (__half*)(sm + SM_C);

    const int b = blockIdx.x;
    const int t = threadIdx.x;
    const int lane = t & 31, w = t >> 5;
    const int mat = lane >> 3, rr = lane & 7;
    const __half* gx = g_xs + (size_t)b * S_DIM * D_DIM;

    // load G[b] (8KB) into smem with GC_STR padding
    {
        const uint4* src = (const uint4*)&g_G[(size_t)(b * 256 + t) * 16];
        uint4 v0 = src[0], v1 = src[1];
        *(uint4*)&Gsm[t * GC_STR] = v0;
        *(uint4*)&Gsm[t * GC_STR + 8] = v1;
    }

    const int wmA = w >> 1, wnA = w & 1;
    const uint32_t xtA_off = (uint32_t)(((wmA * 16 + (mat & 1) * 8 + rr) * XT_STR + (mat >> 1) * 8) * 2);
    const uint32_t gc_off  = (uint32_t)((((mat & 1) * 8 + rr) * GC_STR + (mat >> 1) * 8) * 2);
    const uint32_t xtB_off = (uint32_t)((((mat >> 1) * 8 + rr) * XT_STR + w * 32 + (mat & 1) * 8) * 2);

    const int ldr = t >> 2;
    const int ldc0 = (t & 3) * 8;

    float accB[2][2][4];
#pragma unroll
    for (int i = 0; i < 2; i++)
#pragma unroll
        for (int j = 0; j < 2; j++)
#pragma unroll
            for (int q = 0; q < 4; q++) accB[i][j][q] = 0.f;

    issue_tile(smb, 0, gx, 0, ldr, ldc0);
    __syncthreads();  // Gsm ready (and covers first tile ordering)

    for (int tile = 0; tile < 8; tile++) {
        if (tile < 7) { issue_tile(smb, (tile + 1) & 1, gx, tile + 1, ldr, ldc0); CPWAIT(1); }
        else CPWAIT(0);
        __syncthreads();
        const uint32_t xb = smb + (uint32_t)(tile & 1) * 33792u;

        // phase A: logits (two independent mma chains)
        float accA0[4] = {0.f, 0.f, 0.f, 0.f};
        float accA1[4] = {0.f, 0.f, 0.f, 0.f};
#pragma unroll
        for (int ks = 0; ks < 16; ks += 2) {
            uint32_t Af0[4], Bf0[4], Af1[4], Bf1[4];
            LDMX4(Af0, xb + xtA_off + ks * 32);
            LDMX4T(Bf0, smb + SM_G + gc_off + (uint32_t)(ks * 16 * GC_STR * 2));
            LDMX4(Af1, xb + xtA_off + (ks + 1) * 32);
            LDMX4T(Bf1, smb + SM_G + gc_off + (uint32_t)((ks + 1) * 16 * GC_STR * 2));
            MMA_FP16(accA0, Af0, Bf0[wnA * 2], Bf0[wnA * 2 + 1]);
            MMA_FP16(accA1, Af1, Bf1[wnA * 2], Bf1[wnA * 2 + 1]);
        }
        {
            const int sl = wmA * 16 + (lane >> 2);
            const int nc = wnA * 8 + (lane & 3) * 2;
            Lsm[sl * 17 + nc] = accA0[0] + accA1[0];
            Lsm[sl * 17 + nc + 1] = accA0[1] + accA1[1];
            Lsm[(sl + 8) * 17 + nc] = accA0[2] + accA1[2];
            Lsm[(sl + 8) * 17 + nc + 1] = accA0[3] + accA1[3];
        }
        __syncthreads();

        // softmax: thread group of 4 per s (s = t>>2, quarter q = t&3)
        {
            const int sl = t >> 2, q = t & 3;
            float bv[4];
            float mx = -1e30f;
#pragma unroll
            for (int j = 0; j < 4; j++) {
                bv[j] = Lsm[sl * 17 + q * 4 + j];
                mx = fmaxf(mx, bv[j]);
            }
#pragma unroll
            for (int o = 1; o < 4; o <<= 1)
                mx = fmaxf(mx, __shfl_xor_sync(0xffffffffu, mx, o));
            float den = 0.f;
#pragma unroll
            for (int j = 0; j < 4; j++) { bv[j] = __expf(bv[j] - mx); den += bv[j]; }
#pragma unroll
            for (int o = 1; o < 4; o <<= 1)
                den += __shfl_xor_sync(0xffffffffu, den, o);
            const float inv = 1.f / den;
            *(__half2*)&Csm[sl * GC_STR + q * 4] = __floats2half2_rn(bv[0] * inv, bv[1] * inv);
            *(__half2*)&Csm[sl * GC_STR + q * 4 + 2] = __floats2half2_rn(bv[2] * inv, bv[3] * inv);
        }
        __syncthreads();

        // phase B: y^T[k32, n16] += x^T . c
#pragma unroll
        for (int ks = 0; ks < 4; ks++) {
            uint32_t Bf[4];
            LDMX4T(Bf, smb + SM_C + gc_off + (uint32_t)(ks * 16 * GC_STR * 2));
#pragma unroll
            for (int mf = 0; mf < 2; mf++) {
                uint32_t Af[4];
                LDMX4T(Af, xb + xtB_off + (uint32_t)(mf * 16 * 2) +
                           (uint32_t)(ks * 16 * XT_STR * 2));
                MMA_FP16(accB[mf][0], Af, Bf[0], Bf[1]);
                MMA_FP16(accB[mf][1], Af, Bf[2], Bf[3]);
            }
        }
        __syncthreads();
    }

    // write y[b][k][n] fp32
#pragma unroll
    for (int mf = 0; mf < 2; mf++) {
        const int kx = w * 32 + mf * 16 + (lane >> 2);
#pragma unroll
        for (int h = 0; h < 2; h++) {
            const int nc = h * 8 + (lane & 3) * 2;
            float* p0 = &g_y[(size_t)(b * 256 + kx) * 16 + nc];
            float* p1 = &g_y[(size_t)(b * 256 + kx + 8) * 16 + nc];
            *(float2*)p0 = make_float2(accB[mf][h][0], accB[mf][h][1]);
            *(float2*)p1 = make_float2(accB[mf][h][2], accB[mf][h][3]);
        }
    }
}

extern "C" void kernel_launch(void* const* d_in, const int* in_sizes, int n_in,
                              void* d_out, int out_size) {
    const float* x = (const float*)d_in[0];
    const float* W = (const float*)d_in[1];
    float* out = (float*)d_out;

    cudaFuncSetAttribute(route_pass, cudaFuncAttributeMaxDynamicSharedMemorySize, SM_TOTAL);

    split_w<<<512, 256>>>(W);              // + zero xsum
    split_x<<<dim3(256, 4), 256>>>(x);     // convert + xsum
    dim3 g16x8(16, 8);
    squash_k<<<g16x8, 256>>>(W, 0, 0, out);   // out0 from xsum
    gmat_k<<<g16x8, 256>>>(W);                // G0
    route_pass<<<256, 256, SM_TOTAL>>>();     // y0
    squash_k<<<g16x8, 256>>>(W, 1, 0, out);   // out1
    gmat_k<<<g16x8, 256>>>(W);                // G1
    route_pass<<<256, 256, SM_TOTAL>>>();     // y1
    squash_k<<<g16x8, 256>>>(W, 1, 1, out);   // final -> out
}

// round 16
// speedup vs baseline: 1.5531x; 1.3780x over previous
#include <cuda_runtime.h>
#include <cuda_fp16.h>
#include <cstdint>

#define NC 16
#define S_DIM 512
#define D_DIM 256
#define O_DIM 512
#define B_DIM 256

__device__ __half g_xs[(size_t)B_DIM * S_DIM * D_DIM];   // x fp16 [b][s][k]
__device__ float  g_xsum[B_DIM * D_DIM];                 // per-batch col sums of x
__device__ __half g_G[(size_t)B_DIM * NC * D_DIM];       // G [b][n][k] fp16
__device__ float  g_y[(size_t)B_DIM * NC * D_DIM];       // y [b][n][k] fp32

// ---------------- PTX helpers ----------------
#define LDMX4(r, addr)                                                                   \
    asm volatile("ldmatrix.sync.aligned.m8n8.x4.shared.b16 {%0,%1,%2,%3}, [%4];"         \
                 : "=r"((r)[0]), "=r"((r)[1]), "=r"((r)[2]), "=r"((r)[3]) : "r"(addr))
#define LDMX4T(r, addr)                                                                  \
    asm volatile("ldmatrix.sync.aligned.m8n8.x4.trans.shared.b16 {%0,%1,%2,%3}, [%4];"   \
                 : "=r"((r)[0]), "=r"((r)[1]), "=r"((r)[2]), "=r"((r)[3]) : "r"(addr))
#define MMA_FP16(d, a, b0, b1)                                                           \
    asm volatile("mma.sync.aligned.m16n8k16.row.col.f32.f16.f16.f32 "                    \
                 "{%0,%1,%2,%3}, {%4,%5,%6,%7}, {%8,%9}, {%0,%1,%2,%3};"                 \
                 : "+f"((d)[0]), "+f"((d)[1]), "+f"((d)[2]), "+f"((d)[3])                \
                 : "r"((a)[0]), "r"((a)[1]), "r"((a)[2]), "r"((a)[3]), "r"(b0), "r"(b1))
#define CP16(dst, src)                                                                   \
    asm volatile("cp.async.cg.shared.global [%0], [%1], 16;" :: "r"(dst), "l"(src))
#define CPCOMMIT() asm volatile("cp.async.commit_group;")
#define CPWAIT(n)  asm volatile("cp.async.wait_group %0;" :: "n"(n))

__device__ __forceinline__ uint32_t smem_u32(const void* p) {
    uint32_t a;
    asm("{ .reg .u64 t; cvta.to.shared.u64 t, %1; cvt.u32.u64 %0, t; }" : "=r"(a) : "l"(p));
    return a;
}

// ---------------- split_x: convert + partial col sums ----------------
__global__ __launch_bounds__(256) void split_x(const float* __restrict__ x) {
    __shared__ float sums[4][256];
    const int b = blockIdx.x, sq = blockIdx.y, t = threadIdx.x;
    const int kq = t & 63, sg = t >> 6;
    float4 s4 = make_float4(0.f, 0.f, 0.f, 0.f);
    for (int s = sq * 128 + sg; s < sq * 128 + 128; s += 4) {
        const size_t base = ((size_t)(b * S_DIM + s)) * D_DIM + kq * 4;
        const float4 f = *(const float4*)&x[base];
        __half2 h0 = __floats2half2_rn(f.x, f.y);
        __half2 h1 = __floats2half2_rn(f.z, f.w);
        *(uint2*)&g_xs[base] = make_uint2(*(uint32_t*)&h0, *(uint32_t*)&h1);
        s4.x += f.x; s4.y += f.y; s4.z += f.z; s4.w += f.w;
    }
    *(float4*)&sums[sg][kq * 4] = s4;
    __syncthreads();
    atomicAdd(&g_xsum[b * 256 + t], sums[0][t] + sums[1][t] + sums[2][t] + sums[3][t]);
}

__global__ __launch_bounds__(256) void zero_xsum() {
    g_xsum[blockIdx.x * 256 + threadIdx.x] = 0.f;
}

// ---------------- squash_gmat: out = squash(scale*Y·W_n); G = W_n·out ----------------
// grid (16 n, 8 bgroup), block 256
__global__ __launch_bounds__(256) void squash_gmat(const float* __restrict__ W,
                                                   int mode,    // 0: Y=xsum/16, 1: Y=g_y
                                                   int final,   // 1: write out, skip gmat
                                                   float* __restrict__ outp) {
    __shared__ float Wsm[256 * 33];
    __shared__ float osm[32 * 33];
    const int n = blockIdx.x, bg = blockIdx.y, t = threadIdx.x;
#pragma unroll
    for (int d = 0; d < 32; d++)
        Wsm[t * 33 + d] = W[(size_t)t * 512 + n * 32 + d];
    __syncthreads();

    const int d = t & 31, bsub = t >> 5;
    float acc[4] = {0.f, 0.f, 0.f, 0.f};
#pragma unroll 2
    for (int k = 0; k < 256; k++) {
        const float wv = Wsm[k * 33 + d];
#pragma unroll
        for (int j = 0; j < 4; j++) {
            const int bidx = bg * 32 + bsub + 8 * j;
            const float yv = mode ? g_y[((size_t)(bidx * 16 + n)) * 256 + k]
                                  : g_xsum[bidx * 256 + k];
            acc[j] += yv * wv;
        }
    }
#pragma unroll
    for (int j = 0; j < 4; j++) {
        float v = mode ? acc[j] : acc[j] * (1.f / 16.f);
        float ss = v * v;
#pragma unroll
        for (int o = 16; o > 0; o >>= 1) ss += __shfl_xor_sync(0xffffffffu, ss, o);
        const float r = v / sqrtf(ss + 1e-7f);
        if (final) outp[(size_t)(bg * 32 + bsub + 8 * j) * 512 + n * 32 + d] = r;
        else osm[(bsub + 8 * j) * 33 + d] = r;
    }

    if (!final) {
        __syncthreads();
        const int k = t;
#pragma unroll 2
        for (int bl = 0; bl < 32; bl++) {
            float a0 = 0.f, a1 = 0.f;
#pragma unroll
            for (int dd = 0; dd < 32; dd += 2) {
                a0 += osm[bl * 33 + dd] * Wsm[k * 33 + dd];
                a1 += osm[bl * 33 + dd + 1] * Wsm[k * 33 + dd + 1];
            }
            g_G[((size_t)((bg * 32 + bl) * 16 + n)) * 256 + k] = __float2half(a0 + a1);
        }
    }
}

// ---------------- route_pass: per-batch tile loop ----------------
#define XT_STR 264
#define GC_STR 24
#define SM_XT0   0           // 64*264*2 = 33792
#define SM_XT1   33792
#define SM_G     67584       // 256*24*2 = 12288
#define SM_C     79872       // 64*24*2 = 3072
#define SM_L     82944       // 64*17*4 = 4352
#define SM_TOTAL 87296

__device__ __forceinline__ void issue_tile(uint32_t smb, int buf, const __half* gx,
                                           int tile, int ldr, int ldc0) {
    const uint32_t dst = smb + (uint32_t)buf * 33792u + (uint32_t)(ldr * XT_STR * 2);
    const uint64_t src = __cvta_generic_to_global(gx + (size_t)(tile * 64 + ldr) * D_DIM);
#pragma unroll
    for (int j = 0; j < 8; j++)
        CP16(dst + (uint32_t)(ldc0 + j) * 16u, src + (uint64_t)(ldc0 + j) * 16u);
    CPCOMMIT();
}

__global__ __launch_bounds__(256, 2) void route_pass() {
    extern __shared__ char sm[];
    const uint32_t smb = smem_u32(sm);
    float* Lsm  = (float*)(sm + SM_L);
    __half* Gsm = (__half*)(sm + SM_G);
    __half* Csm = (__half*)(sm + SM_C);

    const int b = blockIdx.x;
    const int t = threadIdx.x;
    const int lane = t & 31, w = t >> 5;
    const int mat = lane >> 3, rr = lane & 7;
    const __half* gx = g_xs + (size_t)b * S_DIM * D_DIM;

    // stage G[b] from [n][k] into Gsm[k][n] (coalesced 32B/thread reads)
    {
        const int gn = t >> 4;             // n
        const int gk = (t & 15) * 16;      // k base
        const __half* src = &g_G[((size_t)(b * 16 + gn)) * 256 + gk];
        uint4 v0 = *(const uint4*)src;
        uint4 v1 = *(const uint4*)(src + 8);
        const __half* hv0 = (const __half*)&v0;
        const __half* hv1 = (const __half*)&v1;
#pragma unroll
        for (int j = 0; j < 8; j++) {
            Gsm[(gk + j) * GC_STR + gn] = hv0[j];
            Gsm[(gk + 8 + j) * GC_STR + gn] = hv1[j];
        }
    }

    const int wmA = w >> 1, wnA = w & 1;
    const uint32_t xtA_off = (uint32_t)(((wmA * 16 + (mat & 1) * 8 + rr) * XT_STR + (mat >> 1) * 8) * 2);
    const uint32_t gc_off  = (uint32_t)((((mat & 1) * 8 + rr) * GC_STR + (mat >> 1) * 8) * 2);
    const uint32_t xtB_off = (uint32_t)((((mat >> 1) * 8 + rr) * XT_STR + w * 32 + (mat & 1) * 8) * 2);

    const int ldr = t >> 2;
    const int ldc0 = (t & 3) * 8;

    float accB[2][2][4];
#pragma unroll
    for (int i = 0; i < 2; i++)
#pragma unroll
        for (int j = 0; j < 2; j++)
#pragma unroll
            for (int q = 0; q < 4; q++) accB[i][j][q] = 0.f;

    issue_tile(smb, 0, gx, 0, ldr, ldc0);
    __syncthreads();  // Gsm ready

    for (int tile = 0; tile < 8; tile++) {
        if (tile < 7) { issue_tile(smb, (tile + 1) & 1, gx, tile + 1, ldr, ldc0); CPWAIT(1); }
        else CPWAIT(0);
        __syncthreads();
        const uint32_t xb = smb + (uint32_t)(tile & 1) * 33792u;

        // phase A: logits
        float accA0[4] = {0.f, 0.f, 0.f, 0.f};
        float accA1[4] = {0.f, 0.f, 0.f, 0.f};
#pragma unroll
        for (int ks = 0; ks < 16; ks += 2) {
            uint32_t Af0[4], Bf0[4], Af1[4], Bf1[4];
            LDMX4(Af0, xb + xtA_off + ks * 32);
            LDMX4T(Bf0, smb + SM_G + gc_off + (uint32_t)(ks * 16 * GC_STR * 2));
            LDMX4(Af1, xb + xtA_off + (ks + 1) * 32);
            LDMX4T(Bf1, smb + SM_G + gc_off + (uint32_t)((ks + 1) * 16 * GC_STR * 2));
            MMA_FP16(accA0, Af0, Bf0[wnA * 2], Bf0[wnA * 2 + 1]);
            MMA_FP16(accA1, Af1, Bf1[wnA * 2], Bf1[wnA * 2 + 1]);
        }
        {
            const int sl = wmA * 16 + (lane >> 2);
            const int nc = wnA * 8 + (lane & 3) * 2;
            Lsm[sl * 17 + nc] = accA0[0] + accA1[0];
            Lsm[sl * 17 + nc + 1] = accA0[1] + accA1[1];
            Lsm[(sl + 8) * 17 + nc] = accA0[2] + accA1[2];
            Lsm[(sl + 8) * 17 + nc + 1] = accA0[3] + accA1[3];
        }
        __syncthreads();

        // softmax: 4 threads per s
        {
            const int sl = t >> 2, q = t & 3;
            float bv[4];
            float mx = -1e30f;
#pragma unroll
            for (int j = 0; j < 4; j++) {
                bv[j] = Lsm[sl * 17 + q * 4 + j];
                mx = fmaxf(mx, bv[j]);
            }
#pragma unroll
            for (int o = 1; o < 4; o <<= 1)
                mx = fmaxf(mx, __shfl_xor_sync(0xffffffffu, mx, o));
            float den = 0.f;
#pragma unroll
            for (int j = 0; j < 4; j++) { bv[j] = __expf(bv[j] - mx); den += bv[j]; }
#pragma unroll
            for (int o = 1; o < 4; o <<= 1)
                den += __shfl_xor_sync(0xffffffffu, den, o);
            const float inv = 1.f / den;
            *(__half2*)&Csm[sl * GC_STR + q * 4] = __floats2half2_rn(bv[0] * inv, bv[1] * inv);
            *(__half2*)&Csm[sl * GC_STR + q * 4 + 2] = __floats2half2_rn(bv[2] * inv, bv[3] * inv);
        }
        __syncthreads();

        // phase B: y^T += x^T . c
#pragma unroll
        for (int ks = 0; ks < 4; ks++) {
            uint32_t Bf[4];
            LDMX4T(Bf, smb + SM_C + gc_off + (uint32_t)(ks * 16 * GC_STR * 2));
#pragma unroll
            for (int mf = 0; mf < 2; mf++) {
                uint32_t Af[4];
                LDMX4T(Af, xb + xtB_off + (uint32_t)(mf * 16 * 2) +
                           (uint32_t)(ks * 16 * XT_STR * 2));
                MMA_FP16(accB[mf][0], Af, Bf[0], Bf[1]);
                MMA_FP16(accB[mf][1], Af, Bf[2], Bf[3]);
            }
        }
        __syncthreads();
    }

    // stage y^T[k][n] into (free) xt buffer, then coalesced [n][k] writes
    float* yst = (float*)sm;  // 256*17*4 = 17408 B
#pragma unroll
    for (int mf = 0; mf < 2; mf++) {
        const int kx = w * 32 + mf * 16 + (lane >> 2);
#pragma unroll
        for (int h = 0; h < 2; h++) {
            const int nc = h * 8 + (lane & 3) * 2;
            yst[kx * 17 + nc] = accB[mf][h][0];
            yst[kx * 17 + nc + 1] = accB[mf][h][1];
            yst[(kx + 8) * 17 + nc] = accB[mf][h][2];
            yst[(kx + 8) * 17 + nc + 1] = accB[mf][h][3];
        }
    }
    __syncthreads();
    {
        const int n = t >> 4;
        const int kb = (t & 15) * 16;
        float* dst = &g_y[((size_t)(b * 16 + n)) * 256 + kb];
#pragma unroll
        for (int j4 = 0; j4 < 4; j4++) {
            float4 v;
            v.x = yst[(kb + j4 * 4 + 0) * 17 + n];
            v.y = yst[(kb + j4 * 4 + 1) * 17 + n];
            v.z = yst[(kb + j4 * 4 + 2) * 17 + n];
            v.w = yst[(kb + j4 * 4 + 3) * 17 + n];
            *(float4*)&dst[j4 * 4] = v;
        }
    }
}

extern "C" void kernel_launch(void* const* d_in, const int* in_sizes, int n_in,
                              void* d_out, int out_size) {
    const float* x = (const float*)d_in[0];
    const float* W = (const float*)d_in[1];
    float* out = (float*)d_out;

    cudaFuncSetAttribute(route_pass, cudaFuncAttributeMaxDynamicSharedMemorySize, SM_TOTAL);

    zero_xsum<<<256, 256>>>();
    split_x<<<dim3(256, 4), 256>>>(x);
    dim3 g16x8(16, 8);
    squash_gmat<<<g16x8, 256>>>(W, 0, 0, out);   // out0 + G0
    route_pass<<<256, 256, SM_TOTAL>>>();        // y0
    squash_gmat<<<g16x8, 256>>>(W, 1, 0, out);   // out1 + G1
    route_pass<<<256, 256, SM_TOTAL>>>();        // y1
    squash_gmat<<<g16x8, 256>>>(W, 1, 1, out);   // final
}

// round 17
// speedup vs baseline: 1.5883x; 1.0227x over previous
#include <cuda_runtime.h>
#include <cuda_fp16.h>
#include <cstdint>

#define NC 16
#define S_DIM 512
#define D_DIM 256
#define O_DIM 512
#define B_DIM 256

__device__ __half g_xs[(size_t)B_DIM * S_DIM * D_DIM];   // x fp16 [b][s][k]
__device__ float  g_xsum[B_DIM * D_DIM];
__device__ __half g_G[(size_t)B_DIM * NC * D_DIM];       // G [b][n][k] fp16
__device__ float  g_y[(size_t)B_DIM * NC * D_DIM];       // y [b][n][k] fp32

// ---------------- PTX helpers ----------------
#define LDMX4(r, addr)                                                                   \
    asm volatile("ldmatrix.sync.aligned.m8n8.x4.shared.b16 {%0,%1,%2,%3}, [%4];"         \
                 : "=r"((r)[0]), "=r"((r)[1]), "=r"((r)[2]), "=r"((r)[3]) : "r"(addr))
#define LDMX4T(r, addr)                                                                  \
    asm volatile("ldmatrix.sync.aligned.m8n8.x4.trans.shared.b16 {%0,%1,%2,%3}, [%4];"   \
                 : "=r"((r)[0]), "=r"((r)[1]), "=r"((r)[2]), "=r"((r)[3]) : "r"(addr))
#define MMA_FP16(d, a, b0, b1)                                                           \
    asm volatile("mma.sync.aligned.m16n8k16.row.col.f32.f16.f16.f32 "                    \
                 "{%0,%1,%2,%3}, {%4,%5,%6,%7}, {%8,%9}, {%0,%1,%2,%3};"                 \
                 : "+f"((d)[0]), "+f"((d)[1]), "+f"((d)[2]), "+f"((d)[3])                \
                 : "r"((a)[0]), "r"((a)[1]), "r"((a)[2]), "r"((a)[3]), "r"(b0), "r"(b1))
#define CP16(dst, src)                                                                   \
    asm volatile("cp.async.cg.shared.global [%0], [%1], 16;" :: "r"(dst), "l"(src))
#define CPCOMMIT() asm volatile("cp.async.commit_group;")
#define CPWAIT(n)  asm volatile("cp.async.wait_group %0;" :: "n"(n))

__device__ __forceinline__ uint32_t smem_u32(const void* p) {
    uint32_t a;
    asm("{ .reg .u64 t; cvta.to.shared.u64 t, %1; cvt.u32.u64 %0, t; }" : "=r"(a) : "l"(p));
    return a;
}

// ---------------- split_x ----------------
__global__ __launch_bounds__(256) void split_x(const float* __restrict__ x) {
    __shared__ float sums[4][256];
    const int b = blockIdx.x, sq = blockIdx.y, t = threadIdx.x;
    const int kq = t & 63, sg = t >> 6;
    float4 s4 = make_float4(0.f, 0.f, 0.f, 0.f);
    for (int s = sq * 128 + sg; s < sq * 128 + 128; s += 4) {
        const size_t base = ((size_t)(b * S_DIM + s)) * D_DIM + kq * 4;
        const float4 f = *(const float4*)&x[base];
        __half2 h0 = __floats2half2_rn(f.x, f.y);
        __half2 h1 = __floats2half2_rn(f.z, f.w);
        *(uint2*)&g_xs[base] = make_uint2(*(uint32_t*)&h0, *(uint32_t*)&h1);
        s4.x += f.x; s4.y += f.y; s4.z += f.z; s4.w += f.w;
    }
    *(float4*)&sums[sg][kq * 4] = s4;
    __syncthreads();
    atomicAdd(&g_xsum[b * 256 + t], sums[0][t] + sums[1][t] + sums[2][t] + sums[3][t]);
}

__global__ __launch_bounds__(256) void zero_xsum() {
    g_xsum[blockIdx.x * 256 + threadIdx.x] = 0.f;
}

// ---------------- squash_gmat (unchanged from R16) ----------------
__global__ __launch_bounds__(256) void squash_gmat(const float* __restrict__ W,
                                                   int mode, int final,
                                                   float* __restrict__ outp) {
    __shared__ float Wsm[256 * 33];
    __shared__ float osm[32 * 33];
    const int n = blockIdx.x, bg = blockIdx.y, t = threadIdx.x;
#pragma unroll
    for (int d = 0; d < 32; d++)
        Wsm[t * 33 + d] = W[(size_t)t * 512 + n * 32 + d];
    __syncthreads();

    const int d = t & 31, bsub = t >> 5;
    float acc[4] = {0.f, 0.f, 0.f, 0.f};
#pragma unroll 2
    for (int k = 0; k < 256; k++) {
        const float wv = Wsm[k * 33 + d];
#pragma unroll
        for (int j = 0; j < 4; j++) {
            const int bidx = bg * 32 + bsub + 8 * j;
            const float yv = mode ? g_y[((size_t)(bidx * 16 + n)) * 256 + k]
                                  : g_xsum[bidx * 256 + k];
            acc[j] += yv * wv;
        }
    }
#pragma unroll
    for (int j = 0; j < 4; j++) {
        float v = mode ? acc[j] : acc[j] * (1.f / 16.f);
        float ss = v * v;
#pragma unroll
        for (int o = 16; o > 0; o >>= 1) ss += __shfl_xor_sync(0xffffffffu, ss, o);
        const float r = v / sqrtf(ss + 1e-7f);
        if (final) outp[(size_t)(bg * 32 + bsub + 8 * j) * 512 + n * 32 + d] = r;
        else osm[(bsub + 8 * j) * 33 + d] = r;
    }

    if (!final) {
        __syncthreads();
        const int k = t;
#pragma unroll 2
        for (int bl = 0; bl < 32; bl++) {
            float a0 = 0.f, a1 = 0.f;
#pragma unroll
            for (int dd = 0; dd < 32; dd += 2) {
                a0 += osm[bl * 33 + dd] * Wsm[k * 33 + dd];
                a1 += osm[bl * 33 + dd + 1] * Wsm[k * 33 + dd + 1];
            }
            g_G[((size_t)((bg * 32 + bl) * 16 + n)) * 256 + k] = __float2half(a0 + a1);
        }
    }
}

// ---------------- route_pass: 32-s tiles, 3 stages, 3 CTAs/SM ----------------
#define XT_STR 264
#define GC_STR 24
#define XTB    16896         // 32*264*2
#define SM_G   50688         // 3*XTB
#define SM_C   62976         // +16*256*... G = 256*24*2 = 12288
#define SM_L   64512         // C = 32*24*2 = 1536
#define SM_TOTAL 68864       // L = 2*32*17*4 = 4352

__device__ __forceinline__ void issue_tile(uint32_t smb, int buf, const __half* gx,
                                           int tile, int ldr, int ldc0) {
    const uint32_t dst = smb + (uint32_t)buf * XTB + (uint32_t)(ldr * XT_STR * 2);
    const uint64_t src = __cvta_generic_to_global(gx + (size_t)(tile * 32 + ldr) * D_DIM);
#pragma unroll
    for (int j = 0; j < 4; j++)
        CP16(dst + (uint32_t)(ldc0 + j) * 16u, src + (uint64_t)(ldc0 + j) * 16u);
    CPCOMMIT();
}

__global__ __launch_bounds__(256, 3) void route_pass() {
    extern __shared__ char sm[];
    const uint32_t smb = smem_u32(sm);
    float* Lsm  = (float*)(sm + SM_L);   // [2][32][17]
    __half* Gsm = (__half*)(sm + SM_G);
    __half* Csm = (__half*)(sm + SM_C);

    const int b = blockIdx.x;
    const int t = threadIdx.x;
    const int lane = t & 31, w = t >> 5;
    const int mat = lane >> 3, rr = lane & 7;
    const __half* gx = g_xs + (size_t)b * S_DIM * D_DIM;

    // stage G[b]: [n][k] -> Gsm[k][n]
    {
        const int gn = t >> 4;
        const int gk = (t & 15) * 16;
        const __half* src = &g_G[((size_t)(b * 16 + gn)) * 256 + gk];
        uint4 v0 = *(const uint4*)src;
        uint4 v1 = *(const uint4*)(src + 8);
        const __half* hv0 = (const __half*)&v0;
        const __half* hv1 = (const __half*)&v1;
#pragma unroll
        for (int j = 0; j < 8; j++) {
            Gsm[(gk + j) * GC_STR + gn] = hv0[j];
            Gsm[(gk + 8 + j) * GC_STR + gn] = hv1[j];
        }
    }

    // phase A warp roles: sm2 (s-half), wn (n-half), wk (k-half: 8 ks each)
    const int smh = w & 1, wn = (w >> 1) & 1, wk = w >> 2;
    const uint32_t xtA_off = (uint32_t)(((smh * 16 + (mat & 1) * 8 + rr) * XT_STR + (mat >> 1) * 8) * 2);
    const uint32_t gc_off  = (uint32_t)((((mat & 1) * 8 + rr) * GC_STR + (mat >> 1) * 8) * 2);
    // phase B: warp = k-block kb
    const int kb = w;
    const uint32_t xtB_off = (uint32_t)((((mat >> 1) * 8 + rr) * XT_STR + kb * 32 + (mat & 1) * 8) * 2);

    const int ldr = t >> 3;          // 0..31
    const int ldc0 = (t & 7) * 4;    // 4 chunks of 16B

    float accB[2][2][4];
#pragma unroll
    for (int i = 0; i < 2; i++)
#pragma unroll
        for (int j = 0; j < 2; j++)
#pragma unroll
            for (int q = 0; q < 4; q++) accB[i][j][q] = 0.f;

    issue_tile(smb, 0, gx, 0, ldr, ldc0);
    issue_tile(smb, 1, gx, 1, ldr, ldc0);
    __syncthreads();  // Gsm ready

    for (int tile = 0; tile < 16; tile++) {
        if (tile < 15) { CPWAIT(1); } else { CPWAIT(0); }
        __syncthreads();
        if (tile < 14) issue_tile(smb, (tile + 2) % 3, gx, tile + 2, ldr, ldc0);
        const uint32_t xb = smb + (uint32_t)(tile % 3) * XTB;

        // ---- phase A: logit partials over this warp's 8 k-steps (2 chains) ----
        float a0[4] = {0.f, 0.f, 0.f, 0.f};
        float a1[4] = {0.f, 0.f, 0.f, 0.f};
#pragma unroll
        for (int j = 0; j < 8; j += 2) {
            const int ks0 = wk * 8 + j, ks1 = ks0 + 1;
            uint32_t Af0[4], Bf0[4], Af1[4], Bf1[4];
            LDMX4(Af0, xb + xtA_off + ks0 * 32);
            LDMX4T(Bf0, smb + SM_G + gc_off + (uint32_t)(ks0 * 16 * GC_STR * 2));
            LDMX4(Af1, xb + xtA_off + ks1 * 32);
            LDMX4T(Bf1, smb + SM_G + gc_off + (uint32_t)(ks1 * 16 * GC_STR * 2));
            MMA_FP16(a0, Af0, Bf0[wn * 2], Bf0[wn * 2 + 1]);
            MMA_FP16(a1, Af1, Bf1[wn * 2], Bf1[wn * 2 + 1]);
        }
        {
            const int sl = smh * 16 + (lane >> 2);
            const int nc = wn * 8 + (lane & 3) * 2;
            float* Lp = &Lsm[(size_t)wk * 32 * 17];
            Lp[sl * 17 + nc] = a0[0] + a1[0];
            Lp[sl * 17 + nc + 1] = a0[1] + a1[1];
            Lp[(sl + 8) * 17 + nc] = a0[2] + a1[2];
            Lp[(sl + 8) * 17 + nc + 1] = a0[3] + a1[3];
        }
        __syncthreads();

        // ---- softmax (128 threads; sums 2 k-partials) ----
        if (t < 128) {
            const int sl = t >> 2, q = t & 3;
            float bv[4];
            float mx = -1e30f;
#pragma unroll
            for (int j = 0; j < 4; j++) {
                bv[j] = Lsm[sl * 17 + q * 4 + j] + Lsm[32 * 17 + sl * 17 + q * 4 + j];
                mx = fmaxf(mx, bv[j]);
            }
#pragma unroll
            for (int o = 1; o < 4; o <<= 1)
                mx = fmaxf(mx, __shfl_xor_sync(0xffffffffu, mx, o));
            float den = 0.f;
#pragma unroll
            for (int j = 0; j < 4; j++) { bv[j] = __expf(bv[j] - mx); den += bv[j]; }
#pragma unroll
            for (int o = 1; o < 4; o <<= 1)
                den += __shfl_xor_sync(0xffffffffu, den, o);
            const float inv = 1.f / den;
            *(__half2*)&Csm[sl * GC_STR + q * 4] = __floats2half2_rn(bv[0] * inv, bv[1] * inv);
            *(__half2*)&Csm[sl * GC_STR + q * 4 + 2] = __floats2half2_rn(bv[2] * inv, bv[3] * inv);
        }
        __syncthreads();

        // ---- phase B: y^T[k32, n16] += x^T . c  (2 s-steps) ----
#pragma unroll
        for (int ks = 0; ks < 2; ks++) {
            uint32_t Bf[4];
            LDMX4T(Bf, smb + SM_C + gc_off + (uint32_t)(ks * 16 * GC_STR * 2));
#pragma unroll
            for (int mf = 0; mf < 2; mf++) {
                uint32_t Af[4];
                LDMX4T(Af, xb + xtB_off + (uint32_t)(mf * 16 * 2) +
                           (uint32_t)(ks * 16 * XT_STR * 2));
                MMA_FP16(accB[mf][0], Af, Bf[0], Bf[1]);
                MMA_FP16(accB[mf][1], Af, Bf[2], Bf[3]);
            }
        }
        __syncthreads();
    }

    // stage y^T[k][n] then coalesced [n][k] writes
    float* yst = (float*)sm;
#pragma unroll
    for (int mf = 0; mf < 2; mf++) {
        const int kx = kb * 32 + mf * 16 + (lane >> 2);
#pragma unroll
        for (int h = 0; h < 2; h++) {
            const int nc = h * 8 + (lane & 3) * 2;
            yst[kx * 17 + nc] = accB[mf][h][0];
            yst[kx * 17 + nc + 1] = accB[mf][h][1];
            yst[(kx + 8) * 17 + nc] = accB[mf][h][2];
            yst[(kx + 8) * 17 + nc + 1] = accB[mf][h][3];
        }
    }
    __syncthreads();
    {
        const int n = t >> 4;
        const int kbb = (t & 15) * 16;
        float* dst = &g_y[((size_t)(b * 16 + n)) * 256 + kbb];
#pragma unroll
        for (int j4 = 0; j4 < 4; j4++) {
            float4 v;
            v.x = yst[(kbb + j4 * 4 + 0) * 17 + n];
            v.y = yst[(kbb + j4 * 4 + 1) * 17 + n];
            v.z = yst[(kbb + j4 * 4 + 2) * 17 + n];
            v.w = yst[(kbb + j4 * 4 + 3) * 17 + n];
            *(float4*)&dst[j4 * 4] = v;
        }
    }
}

extern "C" void kernel_launch(void* const* d_in, const int* in_sizes, int n_in,
                              void* d_out, int out_size) {
    const float* x = (const float*)d_in[0];
    const float* W = (const float*)d_in[1];
    float* out = (float*)d_out;

    cudaFuncSetAttribute(route_pass, cudaFuncAttributeMaxDynamicSharedMemorySize, SM_TOTAL);

    zero_xsum<<<256, 256>>>();
    split_x<<<dim3(256, 4), 256>>>(x);
    dim3 g16x8(16, 8);
    squash_gmat<<<g16x8, 256>>>(W, 0, 0, out);   // out0 + G0
    route_pass<<<256, 256, SM_TOTAL>>>();        // y0
    squash_gmat<<<g16x8, 256>>>(W, 1, 0, out);   // out1 + G1
    route_pass<<<256, 256, SM_TOTAL>>>();        // y1
    squash_gmat<<<g16x8, 256>>>(W, 1, 1, out);   // final
}